// round 8
// baseline (speedup 1.0000x reference)
#include <cuda_runtime.h>
#include <math.h>

#define B_   4
#define S_   2048
#define N_   2049
#define D_   512
#define R_   64
#define L_   2
#define WINW 32
#define E_   66      // 65 window edges + anchor
#define M_   (B_*N_)
#define SCALE 0.125f

// ---------------- scratch (no allocs allowed) ----------------
__device__ float g_val[M_*D_];
__device__ float g_dval[M_*D_];
__device__ float g_q[M_*R_];
__device__ float g_k[M_*R_];
__device__ float g_we[M_*E_];
__device__ float g_state[M_];
__device__ float g_dstate[M_];

// ---------------- block reduction (256 threads) ----------------
__device__ __forceinline__ float blkSum256(float v, float* sh) {
    int lane = threadIdx.x & 31, w = threadIdx.x >> 5;
    #pragma unroll
    for (int o = 16; o; o >>= 1) v += __shfl_xor_sync(0xffffffffu, v, o);
    if (lane == 0) sh[w] = v;
    __syncthreads();
    if (w == 0) {
        float x = (lane < 8) ? sh[lane] : 0.f;
        #pragma unroll
        for (int o = 4; o; o >>= 1) x += __shfl_xor_sync(0xffffffffu, x, o);
        if (lane == 0) sh[0] = x;
    }
    __syncthreads();
    float r = sh[0];
    __syncthreads();
    return r;
}

// ---------------- K1: embedding + input LN + state proj ----------------
__global__ void k_embed(const int* __restrict__ ids, const float* __restrict__ emb,
                        const float* __restrict__ pos, const float* __restrict__ aval,
                        const float* __restrict__ ast,
                        const float* __restrict__ ing, const float* __restrict__ inb,
                        const float* __restrict__ spw, const float* __restrict__ spb) {
    __shared__ float sh[8];
    int bn = blockIdx.x;
    int b = bn / N_, n = bn % N_;
    float* vrow = g_val + (size_t)bn * D_;
    int t = threadIdx.x;
    if (n == 0) {
        vrow[t]       = aval[t];
        vrow[t + 256] = aval[t + 256];
        if (t == 0) g_state[bn] = ast[0];
        return;
    }
    int id = ids[b * S_ + (n - 1)];
    float x0 = emb[(size_t)id * D_ + t]       + pos[(size_t)(n - 1) * D_ + t];
    float x1 = emb[(size_t)id * D_ + t + 256] + pos[(size_t)(n - 1) * D_ + t + 256];
    float m  = blkSum256(x0 + x1, sh) * (1.f / D_);
    float d0 = x0 - m, d1 = x1 - m;
    float var = blkSum256(d0 * d0 + d1 * d1, sh) * (1.f / D_);
    float inv = rsqrtf(var + 1e-5f);
    float y0 = d0 * inv * ing[t]       + inb[t];
    float y1 = d1 * inv * ing[t + 256] + inb[t + 256];
    vrow[t] = y0; vrow[t + 256] = y1;
    float dp = blkSum256(y0 * spw[t] + y1 * spw[t + 256], sh);
    if (t == 0) g_state[bn] = dp + spb[0];
}

// ---------------- K2: q/k projection  [M,512] @ [512,128] ----------------
// 128 threads, 32-row x 128-col tile, thread = 4 rows x (4 q-cols + 4 k-cols)
__global__ __launch_bounds__(128) void k_proj(const float* __restrict__ wq,
                                              const float* __restrict__ wk, int layer) {
    __shared__ float As[32][36];    // [row][kk]
    __shared__ float Bs[32][132];   // [kk][col] cols 0..63=q, 64..127=k
    int m0 = blockIdx.x * 32;
    const float* wqL = wq + (size_t)layer * D_ * R_;
    const float* wkL = wk + (size_t)layer * D_ * R_;
    int t  = threadIdx.x;
    int cg = t & 15;     // col group: q cols cg*4.., k cols 64+cg*4..
    int rg = t >> 4;     // row group: 4 rows each (rg 0..7)
    float acc[4][8];
    #pragma unroll
    for (int i = 0; i < 4; i++)
        #pragma unroll
        for (int j = 0; j < 8; j++) acc[i][j] = 0.f;

    for (int kc = 0; kc < D_; kc += 32) {
        #pragma unroll
        for (int i = t; i < 32 * 8; i += 128) {
            int row = i >> 3, kq = (i & 7) * 4;
            int gr = m0 + row; if (gr >= M_) gr = M_ - 1;
            float4 v = *(const float4*)&g_val[(size_t)gr * D_ + kc + kq];
            *(float4*)&As[row][kq] = v;
        }
        #pragma unroll
        for (int i = t; i < 32 * 32; i += 128) {
            int kk = i >> 5, c4 = (i & 31) * 4;
            float4 v;
            if (c4 < 64) v = *(const float4*)&wqL[(size_t)(kc + kk) * R_ + c4];
            else         v = *(const float4*)&wkL[(size_t)(kc + kk) * R_ + (c4 - 64)];
            *(float4*)&Bs[kk][c4] = v;
        }
        __syncthreads();
        #pragma unroll 8
        for (int kk = 0; kk < 32; kk++) {
            float a[4];
            #pragma unroll
            for (int i = 0; i < 4; i++) a[i] = As[rg * 4 + i][kk];
            float4 b0 = *(const float4*)&Bs[kk][cg * 4];        // q
            float4 b1 = *(const float4*)&Bs[kk][64 + cg * 4];   // k
            #pragma unroll
            for (int i = 0; i < 4; i++) {
                acc[i][0] += a[i] * b0.x; acc[i][1] += a[i] * b0.y;
                acc[i][2] += a[i] * b0.z; acc[i][3] += a[i] * b0.w;
                acc[i][4] += a[i] * b1.x; acc[i][5] += a[i] * b1.y;
                acc[i][6] += a[i] * b1.z; acc[i][7] += a[i] * b1.w;
            }
        }
        __syncthreads();
    }
    #pragma unroll
    for (int i = 0; i < 4; i++) {
        int gr = m0 + rg * 4 + i;
        if (gr >= M_) continue;
        float4 oq = make_float4(acc[i][0], acc[i][1], acc[i][2], acc[i][3]);
        float4 ok = make_float4(acc[i][4], acc[i][5], acc[i][6], acc[i][7]);
        *(float4*)&g_q[(size_t)gr * R_ + cg * 4] = oq;
        *(float4*)&g_k[(size_t)gr * R_ + cg * 4] = ok;
    }
}

// ---------------- K3: scores + signed-abs softmax + dstate ----------------
__device__ __forceinline__ bool edge_valid(int n, int w) {
    if (w < 65) { int p = n + w - WINW; return (p >= 0) && (p < N_); }
    return n > WINW;
}
__device__ __forceinline__ float sgnf(float s) {
    return (s > 0.f) ? 1.f : ((s < 0.f) ? -1.f : 0.f);
}

#define KS_STR 65
__global__ void k_scores() {
    __shared__ float ks[96][KS_STR];
    __shared__ float qs[32][KS_STR];
    __shared__ float k0[64];
    __shared__ float st[97];
    __shared__ float sc[32][68];
    int b  = blockIdx.y;
    int n0 = blockIdx.x * 32;
    int t  = threadIdx.x;
    size_t base = (size_t)b * N_;

    for (int i = t; i < 96 * 64; i += 256) {
        int r = i >> 6, rr = i & 63;
        int g = n0 - WINW + r; g = min(max(g, 0), N_ - 1);
        ks[r][rr] = g_k[(base + g) * R_ + rr];
    }
    for (int i = t; i < 32 * 64; i += 256) {
        int r = i >> 6, rr = i & 63;
        int g = n0 + r; if (g >= N_) g = N_ - 1;
        qs[r][rr] = g_q[(base + g) * R_ + rr];
    }
    if (t < 64) k0[t] = g_k[base * R_ + t];
    if (t < 96) { int g = min(max(n0 - WINW + t, 0), N_ - 1); st[t] = g_state[base + g]; }
    if (t == 96) st[96] = g_state[base];
    __syncthreads();

    {
        int ng2 = t >> 4;
        int wg  = t & 15;
        int i0 = ng2 * 2, w0 = wg * 4;
        float acc[2][4];
        #pragma unroll
        for (int j = 0; j < 2; j++)
            #pragma unroll
            for (int l = 0; l < 4; l++) acc[j][l] = 0.f;
        #pragma unroll 4
        for (int rr = 0; rr < 64; rr++) {
            float q0 = qs[i0][rr];
            float q1 = qs[i0 + 1][rr];
            float kv[5];
            #pragma unroll
            for (int m = 0; m < 5; m++) kv[m] = ks[i0 + w0 + m][rr];
            #pragma unroll
            for (int l = 0; l < 4; l++) {
                acc[0][l] += q0 * kv[l];
                acc[1][l] += q1 * kv[l + 1];
            }
        }
        #pragma unroll
        for (int l = 0; l < 4; l++) {
            sc[i0][w0 + l]     = acc[0][l] * SCALE;
            sc[i0 + 1][w0 + l] = acc[1][l] * SCALE;
        }
    }
    if (t < 64) {
        int i = t >> 1, w = 64 + (t & 1);
        float acc = 0.f;
        if (w == 64) {
            #pragma unroll 8
            for (int rr = 0; rr < 64; rr++) acc += qs[i][rr] * ks[i + 64][rr];
        } else {
            #pragma unroll 8
            for (int rr = 0; rr < 64; rr++) acc += qs[i][rr] * k0[rr];
        }
        sc[i][w] = acc * SCALE;
    }
    __syncthreads();

    int warp = t >> 5, lane = t & 31;
    for (int i = warp; i < 32; i += 8) {
        int n = n0 + i;
        if (n >= N_) continue;
        int w0 = lane, w1 = lane + 32, w2 = (lane < 2) ? 64 + lane : -1;
        float s0 = sc[i][w0], s1 = sc[i][w1];
        float s2 = (w2 >= 0) ? sc[i][w2] : 0.f;
        bool v0 = edge_valid(n, w0);
        bool v1 = edge_valid(n, w1);
        bool v2 = (w2 >= 0) ? edge_valid(n, w2) : false;
        float mx = fmaxf(v0 ? fabsf(s0) : -1e30f,
                   fmaxf(v1 ? fabsf(s1) : -1e30f,
                         v2 ? fabsf(s2) : -1e30f));
        #pragma unroll
        for (int o = 16; o; o >>= 1) mx = fmaxf(mx, __shfl_xor_sync(0xffffffffu, mx, o));
        float e0 = v0 ? expf(fabsf(s0) - mx) : 0.f;
        float e1 = v1 ? expf(fabsf(s1) - mx) : 0.f;
        float e2 = v2 ? expf(fabsf(s2) - mx) : 0.f;
        float sum = e0 + e1 + e2;
        #pragma unroll
        for (int o = 16; o; o >>= 1) sum += __shfl_xor_sync(0xffffffffu, sum, o);
        float invs = 1.f / sum;
        float we0 = sgnf(s0) * e0 * invs;
        float we1 = sgnf(s1) * e1 * invs;
        float we2 = sgnf(s2) * e2 * invs;
        size_t o_ = (base + n) * E_;
        g_we[o_ + w0] = we0;
        g_we[o_ + w1] = we1;
        if (w2 >= 0) g_we[o_ + w2] = we2;
        float ds = we0 * st[i + w0] + we1 * st[i + w1];
        if (lane == 0) ds += we2 * st[i + 64];
        if (lane == 1) ds += we2 * st[96];
        #pragma unroll
        for (int o = 16; o; o >>= 1) ds += __shfl_xor_sync(0xffffffffu, ds, o);
        if (lane == 0) g_dstate[base + n] = ds;
    }
}

// ---------------- K4: dval propagation (vectorized pre-skewed weights) ----------------
// block = 64 nodes x 64 feats, 256 threads, thread = 4 nodes x 4 feats
// pwt[r][n] = we[n][r-n] (zero outside band) -> inner loop: 2x LDS.128 + 16 FFMA
#define DV_NODES 64
#define DV_FEATS 64
#define DV_ROWS  128
#define DV_VSTR  68
#define DV_PSTR  68
// dyn smem: vs[128][68] | pwt[128][68] | wa[64] | v0s[64]  = 70144 B
#define DV_SMEM_FLOATS (DV_ROWS*DV_VSTR + DV_ROWS*DV_PSTR + DV_NODES + DV_FEATS)

__global__ __launch_bounds__(256, 3) void k_dval() {
    extern __shared__ float sm[];
    float* vs  = sm;                                 // [128][68]
    float* pwt = vs + DV_ROWS * DV_VSTR;             // [128][68] pre-skewed weights
    float* wa  = pwt + DV_ROWS * DV_PSTR;            // [64] anchor weights
    float* v0s = wa + DV_NODES;                      // [64]

    int b  = blockIdx.z;
    int dc = blockIdx.y * DV_FEATS;
    int n0 = blockIdx.x * DV_NODES;
    int t  = threadIdx.x;
    size_t base = (size_t)b * N_;

    // stage vs rows (global nodes n0-32+row, clamped): 128 rows x 16 float4
    for (int i = t; i < DV_ROWS * (DV_FEATS / 4); i += 256) {
        int row = i >> 4, c4 = i & 15;
        int g = min(max(n0 - WINW + row, 0), N_ - 1);
        float4 v = *(const float4*)&g_val[(base + g) * D_ + dc + c4 * 4];
        *(float4*)&vs[row * DV_VSTR + c4 * 4] = v;
    }
    // zero pwt (vector stores)
    for (int i = t; i < DV_ROWS * DV_PSTR / 4; i += 256)
        *(float4*)&pwt[i * 4] = make_float4(0.f, 0.f, 0.f, 0.f);
    if (t < 16) *(float4*)&v0s[t * 4] = *(const float4*)&g_val[base * D_ + dc + t * 4];
    __syncthreads();
    // fill pwt[r][n] = we[n][w] with r = n + w, n in [0,64), w in [0,65)
    for (int i = t; i < DV_NODES * 65; i += 256) {
        int node = i / 65, w = i % 65;
        int g = n0 + node; if (g >= N_) g = N_ - 1;
        pwt[(node + w) * DV_PSTR + node] = g_we[(base + g) * E_ + w];
    }
    if (t < DV_NODES) {
        int g = n0 + t; if (g >= N_) g = N_ - 1;
        wa[t] = g_we[(base + g) * E_ + 65];
    }
    __syncthreads();

    int fg = t & 15;          // feat group -> 4 feats
    int ng = t >> 4;          // node group -> 4 nodes
    int i0 = ng * 4;
    int f0 = fg * 4;

    float4 a[4];
    #pragma unroll
    for (int j = 0; j < 4; j++) a[j] = make_float4(0.f, 0.f, 0.f, 0.f);

    // r = i0 + rr; node (i0+j) weight = pwt[r][i0+j] -> one float4 per iteration
    #pragma unroll 4
    for (int rr = 0; rr < 68; rr++) {
        int r = i0 + rr;
        float4 w4 = *(const float4*)&pwt[r * DV_PSTR + i0];
        float4 v  = *(const float4*)&vs[r * DV_VSTR + f0];
        a[0].x += w4.x * v.x; a[0].y += w4.x * v.y; a[0].z += w4.x * v.z; a[0].w += w4.x * v.w;
        a[1].x += w4.y * v.x; a[1].y += w4.y * v.y; a[1].z += w4.y * v.z; a[1].w += w4.y * v.w;
        a[2].x += w4.z * v.x; a[2].y += w4.z * v.y; a[2].z += w4.z * v.z; a[2].w += w4.z * v.w;
        a[3].x += w4.w * v.x; a[3].y += w4.w * v.y; a[3].z += w4.w * v.z; a[3].w += w4.w * v.w;
    }
    {   // anchor edge
        float4 v = *(const float4*)&v0s[f0];
        #pragma unroll
        for (int j = 0; j < 4; j++) {
            float wt = wa[i0 + j];
            a[j].x += wt * v.x; a[j].y += wt * v.y;
            a[j].z += wt * v.z; a[j].w += wt * v.w;
        }
    }
    #pragma unroll
    for (int j = 0; j < 4; j++) {
        int n = n0 + i0 + j;
        if (n < N_) {
            *(float4*)&g_dval[(base + n) * D_ + dc + f0] = a[j];
        }
    }
}

// ---------------- K5: residual + LayerNorm + state update ----------------
__global__ void k_ln(const float* __restrict__ lng, const float* __restrict__ lnb,
                     int layer, float* __restrict__ out) {
    __shared__ float sh[8];
    int bn = blockIdx.x;
    int t  = threadIdx.x;
    float* vrow = g_val  + (size_t)bn * D_;
    float* drow = g_dval + (size_t)bn * D_;
    const float* g  = lng + (size_t)layer * D_;
    const float* bt = lnb + (size_t)layer * D_;
    float x0 = vrow[t]       + drow[t];
    float x1 = vrow[t + 256] + drow[t + 256];
    float m  = blkSum256(x0 + x1, sh) * (1.f / D_);
    float d0 = x0 - m, d1 = x1 - m;
    float var = blkSum256(d0 * d0 + d1 * d1, sh) * (1.f / D_);
    float inv = rsqrtf(var + 1e-5f);
    float y0 = d0 * inv * g[t]       + bt[t];
    float y1 = d1 * inv * g[t + 256] + bt[t + 256];
    float* vdst = out ? (out + M_ + (size_t)bn * D_) : vrow;
    vdst[t]       = y0;
    vdst[t + 256] = y1;
    if (t == 0) {
        float s = g_state[bn] + g_dstate[bn];
        if (out) out[bn] = s;
        else     g_state[bn] = s;
    }
}

// ---------------- host ----------------
extern "C" void kernel_launch(void* const* d_in, const int* in_sizes, int n_in,
                              void* d_out, int out_size) {
    const int*   ids  = (const int*)  d_in[0];
    const float* emb  = (const float*)d_in[1];
    const float* pos  = (const float*)d_in[2];
    const float* aval = (const float*)d_in[3];
    const float* ast  = (const float*)d_in[4];
    const float* ing  = (const float*)d_in[5];
    const float* inb  = (const float*)d_in[6];
    const float* spw  = (const float*)d_in[7];
    const float* spb  = (const float*)d_in[8];
    const float* wq   = (const float*)d_in[9];
    const float* wk   = (const float*)d_in[10];
    const float* lng  = (const float*)d_in[11];
    const float* lnb  = (const float*)d_in[12];
    float* out = (float*)d_out;

    const int dv_smem = DV_SMEM_FLOATS * 4;
    cudaFuncSetAttribute(k_dval, cudaFuncAttributeMaxDynamicSharedMemorySize, dv_smem);

    k_embed<<<M_, 256>>>(ids, emb, pos, aval, ast, ing, inb, spw, spb);
    for (int l = 0; l < L_; l++) {
        k_proj  <<<(M_ + 31) / 32, 128>>>(wq, wk, l);
        k_scores<<<dim3(65, B_), 256>>>();
        k_dval  <<<dim3((N_ + DV_NODES - 1) / DV_NODES, D_ / DV_FEATS, B_), 256, dv_smem>>>();
        k_ln    <<<M_, 256>>>(lng, lnb, l, (l == L_ - 1) ? out : nullptr);
    }
}

// round 9
// speedup vs baseline: 1.0252x; 1.0252x over previous
#include <cuda_runtime.h>
#include <math.h>

#define B_   4
#define S_   2048
#define N_   2049
#define D_   512
#define R_   64
#define L_   2
#define WINW 32
#define E_   66      // 65 window edges + anchor
#define M_   (B_*N_)
#define SCALE 0.125f

// ---------------- scratch (no allocs allowed) ----------------
__device__ float g_val[M_*D_];
__device__ float g_dval[M_*D_];
__device__ float g_q[M_*R_];
__device__ float g_k[M_*R_];
__device__ float g_we[M_*E_];
__device__ float g_state[M_];
__device__ float g_dstate[M_];

// ---------------- block reduction (256 threads) ----------------
__device__ __forceinline__ float blkSum256(float v, float* sh) {
    int lane = threadIdx.x & 31, w = threadIdx.x >> 5;
    #pragma unroll
    for (int o = 16; o; o >>= 1) v += __shfl_xor_sync(0xffffffffu, v, o);
    if (lane == 0) sh[w] = v;
    __syncthreads();
    if (w == 0) {
        float x = (lane < 8) ? sh[lane] : 0.f;
        #pragma unroll
        for (int o = 4; o; o >>= 1) x += __shfl_xor_sync(0xffffffffu, x, o);
        if (lane == 0) sh[0] = x;
    }
    __syncthreads();
    float r = sh[0];
    __syncthreads();
    return r;
}

// ---------------- K1: embedding + input LN + state proj ----------------
__global__ void k_embed(const int* __restrict__ ids, const float* __restrict__ emb,
                        const float* __restrict__ pos, const float* __restrict__ aval,
                        const float* __restrict__ ast,
                        const float* __restrict__ ing, const float* __restrict__ inb,
                        const float* __restrict__ spw, const float* __restrict__ spb) {
    __shared__ float sh[8];
    int bn = blockIdx.x;
    int b = bn / N_, n = bn % N_;
    float* vrow = g_val + (size_t)bn * D_;
    int t = threadIdx.x;
    if (n == 0) {
        vrow[t]       = aval[t];
        vrow[t + 256] = aval[t + 256];
        if (t == 0) g_state[bn] = ast[0];
        return;
    }
    int id = ids[b * S_ + (n - 1)];
    float x0 = emb[(size_t)id * D_ + t]       + pos[(size_t)(n - 1) * D_ + t];
    float x1 = emb[(size_t)id * D_ + t + 256] + pos[(size_t)(n - 1) * D_ + t + 256];
    float m  = blkSum256(x0 + x1, sh) * (1.f / D_);
    float d0 = x0 - m, d1 = x1 - m;
    float var = blkSum256(d0 * d0 + d1 * d1, sh) * (1.f / D_);
    float inv = rsqrtf(var + 1e-5f);
    float y0 = d0 * inv * ing[t]       + inb[t];
    float y1 = d1 * inv * ing[t + 256] + inb[t + 256];
    vrow[t] = y0; vrow[t + 256] = y1;
    float dp = blkSum256(y0 * spw[t] + y1 * spw[t + 256], sh);
    if (t == 0) g_state[bn] = dp + spb[0];
}

// ---------------- K2: q/k projection  [M,512] @ [512,128] ----------------
// 128 threads, 32-row x 128-col tile, thread = 4 rows x (4 q-cols + 4 k-cols)
__global__ __launch_bounds__(128) void k_proj(const float* __restrict__ wq,
                                              const float* __restrict__ wk, int layer) {
    __shared__ float As[32][36];    // [row][kk]
    __shared__ float Bs[32][132];   // [kk][col] cols 0..63=q, 64..127=k
    int m0 = blockIdx.x * 32;
    const float* wqL = wq + (size_t)layer * D_ * R_;
    const float* wkL = wk + (size_t)layer * D_ * R_;
    int t  = threadIdx.x;
    int cg = t & 15;     // col group: q cols cg*4.., k cols 64+cg*4..
    int rg = t >> 4;     // row group: 4 rows each (rg 0..7)
    float acc[4][8];
    #pragma unroll
    for (int i = 0; i < 4; i++)
        #pragma unroll
        for (int j = 0; j < 8; j++) acc[i][j] = 0.f;

    for (int kc = 0; kc < D_; kc += 32) {
        #pragma unroll
        for (int i = t; i < 32 * 8; i += 128) {
            int row = i >> 3, kq = (i & 7) * 4;
            int gr = m0 + row; if (gr >= M_) gr = M_ - 1;
            float4 v = *(const float4*)&g_val[(size_t)gr * D_ + kc + kq];
            *(float4*)&As[row][kq] = v;
        }
        #pragma unroll
        for (int i = t; i < 32 * 32; i += 128) {
            int kk = i >> 5, c4 = (i & 31) * 4;
            float4 v;
            if (c4 < 64) v = *(const float4*)&wqL[(size_t)(kc + kk) * R_ + c4];
            else         v = *(const float4*)&wkL[(size_t)(kc + kk) * R_ + (c4 - 64)];
            *(float4*)&Bs[kk][c4] = v;
        }
        __syncthreads();
        #pragma unroll 8
        for (int kk = 0; kk < 32; kk++) {
            float a[4];
            #pragma unroll
            for (int i = 0; i < 4; i++) a[i] = As[rg * 4 + i][kk];
            float4 b0 = *(const float4*)&Bs[kk][cg * 4];        // q
            float4 b1 = *(const float4*)&Bs[kk][64 + cg * 4];   // k
            #pragma unroll
            for (int i = 0; i < 4; i++) {
                acc[i][0] += a[i] * b0.x; acc[i][1] += a[i] * b0.y;
                acc[i][2] += a[i] * b0.z; acc[i][3] += a[i] * b0.w;
                acc[i][4] += a[i] * b1.x; acc[i][5] += a[i] * b1.y;
                acc[i][6] += a[i] * b1.z; acc[i][7] += a[i] * b1.w;
            }
        }
        __syncthreads();
    }
    #pragma unroll
    for (int i = 0; i < 4; i++) {
        int gr = m0 + rg * 4 + i;
        if (gr >= M_) continue;
        float4 oq = make_float4(acc[i][0], acc[i][1], acc[i][2], acc[i][3]);
        float4 ok = make_float4(acc[i][4], acc[i][5], acc[i][6], acc[i][7]);
        *(float4*)&g_q[(size_t)gr * R_ + cg * 4] = oq;
        *(float4*)&g_k[(size_t)gr * R_ + cg * 4] = ok;
    }
}

// ---------------- K3: scores + signed-abs softmax + dstate ----------------
__device__ __forceinline__ bool edge_valid(int n, int w) {
    if (w < 65) { int p = n + w - WINW; return (p >= 0) && (p < N_); }
    return n > WINW;
}
__device__ __forceinline__ float sgnf(float s) {
    return (s > 0.f) ? 1.f : ((s < 0.f) ? -1.f : 0.f);
}

#define KS_STR 65
__global__ void k_scores() {
    __shared__ float ks[96][KS_STR];
    __shared__ float qs[32][KS_STR];
    __shared__ float k0[64];
    __shared__ float st[97];
    __shared__ float sc[32][68];
    int b  = blockIdx.y;
    int n0 = blockIdx.x * 32;
    int t  = threadIdx.x;
    size_t base = (size_t)b * N_;

    for (int i = t; i < 96 * 64; i += 256) {
        int r = i >> 6, rr = i & 63;
        int g = n0 - WINW + r; g = min(max(g, 0), N_ - 1);
        ks[r][rr] = g_k[(base + g) * R_ + rr];
    }
    for (int i = t; i < 32 * 64; i += 256) {
        int r = i >> 6, rr = i & 63;
        int g = n0 + r; if (g >= N_) g = N_ - 1;
        qs[r][rr] = g_q[(base + g) * R_ + rr];
    }
    if (t < 64) k0[t] = g_k[base * R_ + t];
    if (t < 96) { int g = min(max(n0 - WINW + t, 0), N_ - 1); st[t] = g_state[base + g]; }
    if (t == 96) st[96] = g_state[base];
    __syncthreads();

    {
        int ng2 = t >> 4;
        int wg  = t & 15;
        int i0 = ng2 * 2, w0 = wg * 4;
        float acc[2][4];
        #pragma unroll
        for (int j = 0; j < 2; j++)
            #pragma unroll
            for (int l = 0; l < 4; l++) acc[j][l] = 0.f;
        #pragma unroll 4
        for (int rr = 0; rr < 64; rr++) {
            float q0 = qs[i0][rr];
            float q1 = qs[i0 + 1][rr];
            float kv[5];
            #pragma unroll
            for (int m = 0; m < 5; m++) kv[m] = ks[i0 + w0 + m][rr];
            #pragma unroll
            for (int l = 0; l < 4; l++) {
                acc[0][l] += q0 * kv[l];
                acc[1][l] += q1 * kv[l + 1];
            }
        }
        #pragma unroll
        for (int l = 0; l < 4; l++) {
            sc[i0][w0 + l]     = acc[0][l] * SCALE;
            sc[i0 + 1][w0 + l] = acc[1][l] * SCALE;
        }
    }
    if (t < 64) {
        int i = t >> 1, w = 64 + (t & 1);
        float acc = 0.f;
        if (w == 64) {
            #pragma unroll 8
            for (int rr = 0; rr < 64; rr++) acc += qs[i][rr] * ks[i + 64][rr];
        } else {
            #pragma unroll 8
            for (int rr = 0; rr < 64; rr++) acc += qs[i][rr] * k0[rr];
        }
        sc[i][w] = acc * SCALE;
    }
    __syncthreads();

    int warp = t >> 5, lane = t & 31;
    for (int i = warp; i < 32; i += 8) {
        int n = n0 + i;
        if (n >= N_) continue;
        int w0 = lane, w1 = lane + 32, w2 = (lane < 2) ? 64 + lane : -1;
        float s0 = sc[i][w0], s1 = sc[i][w1];
        float s2 = (w2 >= 0) ? sc[i][w2] : 0.f;
        bool v0 = edge_valid(n, w0);
        bool v1 = edge_valid(n, w1);
        bool v2 = (w2 >= 0) ? edge_valid(n, w2) : false;
        float mx = fmaxf(v0 ? fabsf(s0) : -1e30f,
                   fmaxf(v1 ? fabsf(s1) : -1e30f,
                         v2 ? fabsf(s2) : -1e30f));
        #pragma unroll
        for (int o = 16; o; o >>= 1) mx = fmaxf(mx, __shfl_xor_sync(0xffffffffu, mx, o));
        float e0 = v0 ? expf(fabsf(s0) - mx) : 0.f;
        float e1 = v1 ? expf(fabsf(s1) - mx) : 0.f;
        float e2 = v2 ? expf(fabsf(s2) - mx) : 0.f;
        float sum = e0 + e1 + e2;
        #pragma unroll
        for (int o = 16; o; o >>= 1) sum += __shfl_xor_sync(0xffffffffu, sum, o);
        float invs = 1.f / sum;
        float we0 = sgnf(s0) * e0 * invs;
        float we1 = sgnf(s1) * e1 * invs;
        float we2 = sgnf(s2) * e2 * invs;
        size_t o_ = (base + n) * E_;
        g_we[o_ + w0] = we0;
        g_we[o_ + w1] = we1;
        if (w2 >= 0) g_we[o_ + w2] = we2;
        float ds = we0 * st[i + w0] + we1 * st[i + w1];
        if (lane == 0) ds += we2 * st[i + 64];
        if (lane == 1) ds += we2 * st[96];
        #pragma unroll
        for (int o = 16; o; o >>= 1) ds += __shfl_xor_sync(0xffffffffu, ds, o);
        if (lane == 0) g_dstate[base + n] = ds;
    }
}

// ---------------- K4: dval propagation (R6 layout + software-pipelined loop) ----------------
// block = 64 nodes x 64 feats, 256 threads, thread = 4 nodes x 4 feats
#define DV_NODES 64
#define DV_FEATS 64
#define DV_ROWS  128
#define DV_VSTR  68
#define DV_WSTR  76
// dyn smem: vs[128][68] | wz[64][76] | wa[64] | v0s[64]  = 54784 B
#define DV_SMEM_FLOATS (DV_ROWS*DV_VSTR + DV_NODES*DV_WSTR + DV_NODES + DV_FEATS)

__global__ __launch_bounds__(256, 4) void k_dval() {
    extern __shared__ float sm[];
    float* vs  = sm;                                 // [128][68]
    float* wz  = vs + DV_ROWS * DV_VSTR;             // [64][76], zero-padded
    float* wa  = wz + DV_NODES * DV_WSTR;            // [64]
    float* v0s = wa + DV_NODES;                      // [64]

    int b  = blockIdx.z;
    int dc = blockIdx.y * DV_FEATS;
    int n0 = blockIdx.x * DV_NODES;
    int t  = threadIdx.x;
    size_t base = (size_t)b * N_;

    // stage vs rows (global nodes n0-32+row, clamped): 128 rows x 16 float4
    for (int i = t; i < DV_ROWS * (DV_FEATS / 4); i += 256) {
        int row = i >> 4, c4 = i & 15;
        int g = min(max(n0 - WINW + row, 0), N_ - 1);
        float4 v = *(const float4*)&g_val[(base + g) * D_ + dc + c4 * 4];
        *(float4*)&vs[row * DV_VSTR + c4 * 4] = v;
    }
    for (int i = t; i < DV_NODES * DV_WSTR; i += 256) wz[i] = 0.f;
    if (t < 16) *(float4*)&v0s[t * 4] = *(const float4*)&g_val[base * D_ + dc + t * 4];
    __syncthreads();
    for (int i = t; i < DV_NODES * 65; i += 256) {
        int node = i / 65, w = i % 65;
        int g = n0 + node; if (g >= N_) g = N_ - 1;
        wz[node * DV_WSTR + w + 8] = g_we[(base + g) * E_ + w];
    }
    if (t < DV_NODES) {
        int g = n0 + t; if (g >= N_) g = N_ - 1;
        wa[t] = g_we[(base + g) * E_ + 65];
    }
    __syncthreads();

    int fg = t & 15;          // feat group -> 4 feats
    int ng = t >> 4;          // node group -> 4 nodes
    int i0 = ng * 4;
    int f0 = fg * 4;

    float4 a[4];
    #pragma unroll
    for (int j = 0; j < 4; j++) a[j] = make_float4(0.f, 0.f, 0.f, 0.f);

    // software-pipelined: prefetch iteration rr+1's weights + value while FMAing rr
    const float* wzb = wz + i0 * DV_WSTR + 8;   // base for node i0 at rr=0
    float wt[4];
    float4 v;
    #pragma unroll
    for (int j = 0; j < 4; j++) wt[j] = wzb[j * (DV_WSTR - 1)];   // wz[(i0+j)][0 - j + 8]
    v = *(const float4*)&vs[i0 * DV_VSTR + f0];

    #pragma unroll 4
    for (int rr = 0; rr < 68; rr++) {
        float wc[4];
        #pragma unroll
        for (int j = 0; j < 4; j++) wc[j] = wt[j];
        float4 vc = v;
        // prefetch next (clamped on the last iteration; values unused)
        int rn = (rr < 67) ? rr + 1 : 67;
        #pragma unroll
        for (int j = 0; j < 4; j++) wt[j] = wzb[j * (DV_WSTR - 1) + rn];
        v = *(const float4*)&vs[(i0 + rn) * DV_VSTR + f0];
        // FMAs for iteration rr
        a[0].x += wc[0] * vc.x; a[0].y += wc[0] * vc.y; a[0].z += wc[0] * vc.z; a[0].w += wc[0] * vc.w;
        a[1].x += wc[1] * vc.x; a[1].y += wc[1] * vc.y; a[1].z += wc[1] * vc.z; a[1].w += wc[1] * vc.w;
        a[2].x += wc[2] * vc.x; a[2].y += wc[2] * vc.y; a[2].z += wc[2] * vc.z; a[2].w += wc[2] * vc.w;
        a[3].x += wc[3] * vc.x; a[3].y += wc[3] * vc.y; a[3].z += wc[3] * vc.z; a[3].w += wc[3] * vc.w;
    }
    {   // anchor edge
        float4 va = *(const float4*)&v0s[f0];
        #pragma unroll
        for (int j = 0; j < 4; j++) {
            float wtj = wa[i0 + j];
            a[j].x += wtj * va.x; a[j].y += wtj * va.y;
            a[j].z += wtj * va.z; a[j].w += wtj * va.w;
        }
    }
    #pragma unroll
    for (int j = 0; j < 4; j++) {
        int n = n0 + i0 + j;
        if (n < N_) {
            *(float4*)&g_dval[(base + n) * D_ + dc + f0] = a[j];
        }
    }
}

// ---------------- K5: residual + LayerNorm + state update ----------------
__global__ void k_ln(const float* __restrict__ lng, const float* __restrict__ lnb,
                     int layer, float* __restrict__ out) {
    __shared__ float sh[8];
    int bn = blockIdx.x;
    int t  = threadIdx.x;
    float* vrow = g_val  + (size_t)bn * D_;
    float* drow = g_dval + (size_t)bn * D_;
    const float* g  = lng + (size_t)layer * D_;
    const float* bt = lnb + (size_t)layer * D_;
    float x0 = vrow[t]       + drow[t];
    float x1 = vrow[t + 256] + drow[t + 256];
    float m  = blkSum256(x0 + x1, sh) * (1.f / D_);
    float d0 = x0 - m, d1 = x1 - m;
    float var = blkSum256(d0 * d0 + d1 * d1, sh) * (1.f / D_);
    float inv = rsqrtf(var + 1e-5f);
    float y0 = d0 * inv * g[t]       + bt[t];
    float y1 = d1 * inv * g[t + 256] + bt[t + 256];
    float* vdst = out ? (out + M_ + (size_t)bn * D_) : vrow;
    vdst[t]       = y0;
    vdst[t + 256] = y1;
    if (t == 0) {
        float s = g_state[bn] + g_dstate[bn];
        if (out) out[bn] = s;
        else     g_state[bn] = s;
    }
}

// ---------------- host ----------------
extern "C" void kernel_launch(void* const* d_in, const int* in_sizes, int n_in,
                              void* d_out, int out_size) {
    const int*   ids  = (const int*)  d_in[0];
    const float* emb  = (const float*)d_in[1];
    const float* pos  = (const float*)d_in[2];
    const float* aval = (const float*)d_in[3];
    const float* ast  = (const float*)d_in[4];
    const float* ing  = (const float*)d_in[5];
    const float* inb  = (const float*)d_in[6];
    const float* spw  = (const float*)d_in[7];
    const float* spb  = (const float*)d_in[8];
    const float* wq   = (const float*)d_in[9];
    const float* wk   = (const float*)d_in[10];
    const float* lng  = (const float*)d_in[11];
    const float* lnb  = (const float*)d_in[12];
    float* out = (float*)d_out;

    const int dv_smem = DV_SMEM_FLOATS * 4;
    cudaFuncSetAttribute(k_dval, cudaFuncAttributeMaxDynamicSharedMemorySize, dv_smem);

    k_embed<<<M_, 256>>>(ids, emb, pos, aval, ast, ing, inb, spw, spb);
    for (int l = 0; l < L_; l++) {
        k_proj  <<<(M_ + 31) / 32, 128>>>(wq, wk, l);
        k_scores<<<dim3(65, B_), 256>>>();
        k_dval  <<<dim3((N_ + DV_NODES - 1) / DV_NODES, D_ / DV_FEATS, B_), 256, dv_smem>>>();
        k_ln    <<<M_, 256>>>(lng, lnb, l, (l == L_ - 1) ? out : nullptr);
    }
}

// round 10
// speedup vs baseline: 1.0836x; 1.0570x over previous
#include <cuda_runtime.h>
#include <math.h>

#define B_   4
#define S_   2048
#define N_   2049
#define D_   512
#define R_   64
#define L_   2
#define WINW 32
#define E_   66      // 65 window edges + anchor
#define M_   (B_*N_)
#define SCALE 0.125f

// ---------------- scratch (no allocs allowed) ----------------
__device__ float g_val[M_*D_];
__device__ float g_dval[M_*D_];
__device__ float g_q[M_*R_];
__device__ float g_k[M_*R_];
__device__ float g_we[M_*E_];
__device__ float g_state[M_];
__device__ float g_dstate[M_];

// ---------------- packed f32x2 helpers (Blackwell FFMA2) ----------------
__device__ __forceinline__ unsigned long long pk2(float x, float y) {
    unsigned long long r;
    asm("mov.b64 %0, {%1, %2};" : "=l"(r) : "f"(x), "f"(y));
    return r;
}
__device__ __forceinline__ void fma2(unsigned long long& d, unsigned long long a,
                                     unsigned long long b, unsigned long long c) {
    asm("fma.rn.f32x2 %0, %1, %2, %3;" : "=l"(d) : "l"(a), "l"(b), "l"(c));
}
__device__ __forceinline__ void upk2(float& x, float& y, unsigned long long v) {
    asm("mov.b64 {%0, %1}, %2;" : "=f"(x), "=f"(y) : "l"(v));
}

// ---------------- block reduction (256 threads) ----------------
__device__ __forceinline__ float blkSum256(float v, float* sh) {
    int lane = threadIdx.x & 31, w = threadIdx.x >> 5;
    #pragma unroll
    for (int o = 16; o; o >>= 1) v += __shfl_xor_sync(0xffffffffu, v, o);
    if (lane == 0) sh[w] = v;
    __syncthreads();
    if (w == 0) {
        float x = (lane < 8) ? sh[lane] : 0.f;
        #pragma unroll
        for (int o = 4; o; o >>= 1) x += __shfl_xor_sync(0xffffffffu, x, o);
        if (lane == 0) sh[0] = x;
    }
    __syncthreads();
    float r = sh[0];
    __syncthreads();
    return r;
}

// ---------------- K1: embedding + input LN + state proj ----------------
__global__ void k_embed(const int* __restrict__ ids, const float* __restrict__ emb,
                        const float* __restrict__ pos, const float* __restrict__ aval,
                        const float* __restrict__ ast,
                        const float* __restrict__ ing, const float* __restrict__ inb,
                        const float* __restrict__ spw, const float* __restrict__ spb) {
    __shared__ float sh[8];
    int bn = blockIdx.x;
    int b = bn / N_, n = bn % N_;
    float* vrow = g_val + (size_t)bn * D_;
    int t = threadIdx.x;
    if (n == 0) {
        vrow[t]       = aval[t];
        vrow[t + 256] = aval[t + 256];
        if (t == 0) g_state[bn] = ast[0];
        return;
    }
    int id = ids[b * S_ + (n - 1)];
    float x0 = emb[(size_t)id * D_ + t]       + pos[(size_t)(n - 1) * D_ + t];
    float x1 = emb[(size_t)id * D_ + t + 256] + pos[(size_t)(n - 1) * D_ + t + 256];
    float m  = blkSum256(x0 + x1, sh) * (1.f / D_);
    float d0 = x0 - m, d1 = x1 - m;
    float var = blkSum256(d0 * d0 + d1 * d1, sh) * (1.f / D_);
    float inv = rsqrtf(var + 1e-5f);
    float y0 = d0 * inv * ing[t]       + inb[t];
    float y1 = d1 * inv * ing[t + 256] + inb[t + 256];
    vrow[t] = y0; vrow[t + 256] = y1;
    float dp = blkSum256(y0 * spw[t] + y1 * spw[t + 256], sh);
    if (t == 0) g_state[bn] = dp + spb[0];
}

// ---------------- K2: q/k projection  [M,512] @ [512,128], FFMA2 ----------------
// 128 threads, 32-row x 128-col tile, thread = 4 rows x (4 q-cols + 4 k-cols)
__global__ __launch_bounds__(128) void k_proj(const float* __restrict__ wq,
                                              const float* __restrict__ wk, int layer) {
    __shared__ float As[32][36];    // [row][kk]
    __shared__ float Bs[32][132];   // [kk][col] cols 0..63=q, 64..127=k
    int m0 = blockIdx.x * 32;
    const float* wqL = wq + (size_t)layer * D_ * R_;
    const float* wkL = wk + (size_t)layer * D_ * R_;
    int t  = threadIdx.x;
    int cg = t & 15;
    int rg = t >> 4;
    // packed accumulators: [i] x {q01,q23,k01,k23}
    unsigned long long q01[4], q23[4], k01[4], k23[4];
    #pragma unroll
    for (int i = 0; i < 4; i++) { q01[i] = 0ull; q23[i] = 0ull; k01[i] = 0ull; k23[i] = 0ull; }

    for (int kc = 0; kc < D_; kc += 32) {
        #pragma unroll
        for (int i = t; i < 32 * 8; i += 128) {
            int row = i >> 3, kq = (i & 7) * 4;
            int gr = m0 + row; if (gr >= M_) gr = M_ - 1;
            float4 v = *(const float4*)&g_val[(size_t)gr * D_ + kc + kq];
            *(float4*)&As[row][kq] = v;
        }
        #pragma unroll
        for (int i = t; i < 32 * 32; i += 128) {
            int kk = i >> 5, c4 = (i & 31) * 4;
            float4 v;
            if (c4 < 64) v = *(const float4*)&wqL[(size_t)(kc + kk) * R_ + c4];
            else         v = *(const float4*)&wkL[(size_t)(kc + kk) * R_ + (c4 - 64)];
            *(float4*)&Bs[kk][c4] = v;
        }
        __syncthreads();
        #pragma unroll 8
        for (int kk = 0; kk < 32; kk++) {
            unsigned long long ap[4];
            #pragma unroll
            for (int i = 0; i < 4; i++) {
                float av = As[rg * 4 + i][kk];
                ap[i] = pk2(av, av);
            }
            // Bs rows are 16B-aligned: read q/k fragments as packed pairs
            ulonglong2 bq = *(const ulonglong2*)&Bs[kk][cg * 4];
            ulonglong2 bk = *(const ulonglong2*)&Bs[kk][64 + cg * 4];
            #pragma unroll
            for (int i = 0; i < 4; i++) {
                fma2(q01[i], ap[i], bq.x, q01[i]);
                fma2(q23[i], ap[i], bq.y, q23[i]);
                fma2(k01[i], ap[i], bk.x, k01[i]);
                fma2(k23[i], ap[i], bk.y, k23[i]);
            }
        }
        __syncthreads();
    }
    #pragma unroll
    for (int i = 0; i < 4; i++) {
        int gr = m0 + rg * 4 + i;
        if (gr >= M_) continue;
        float4 oq, ok;
        upk2(oq.x, oq.y, q01[i]); upk2(oq.z, oq.w, q23[i]);
        upk2(ok.x, ok.y, k01[i]); upk2(ok.z, ok.w, k23[i]);
        *(float4*)&g_q[(size_t)gr * R_ + cg * 4] = oq;
        *(float4*)&g_k[(size_t)gr * R_ + cg * 4] = ok;
    }
}

// ---------------- K3: scores + signed-abs softmax + dstate ----------------
__device__ __forceinline__ bool edge_valid(int n, int w) {
    if (w < 65) { int p = n + w - WINW; return (p >= 0) && (p < N_); }
    return n > WINW;
}
__device__ __forceinline__ float sgnf(float s) {
    return (s > 0.f) ? 1.f : ((s < 0.f) ? -1.f : 0.f);
}

#define KS_STR 65
__global__ void k_scores() {
    __shared__ float ks[96][KS_STR];
    __shared__ float qs[32][KS_STR];
    __shared__ float k0[64];
    __shared__ float st[97];
    __shared__ float sc[32][68];
    int b  = blockIdx.y;
    int n0 = blockIdx.x * 32;
    int t  = threadIdx.x;
    size_t base = (size_t)b * N_;

    for (int i = t; i < 96 * 64; i += 256) {
        int r = i >> 6, rr = i & 63;
        int g = n0 - WINW + r; g = min(max(g, 0), N_ - 1);
        ks[r][rr] = g_k[(base + g) * R_ + rr];
    }
    for (int i = t; i < 32 * 64; i += 256) {
        int r = i >> 6, rr = i & 63;
        int g = n0 + r; if (g >= N_) g = N_ - 1;
        qs[r][rr] = g_q[(base + g) * R_ + rr];
    }
    if (t < 64) k0[t] = g_k[base * R_ + t];
    if (t < 96) { int g = min(max(n0 - WINW + t, 0), N_ - 1); st[t] = g_state[base + g]; }
    if (t == 96) st[96] = g_state[base];
    __syncthreads();

    {
        int ng2 = t >> 4;
        int wg  = t & 15;
        int i0 = ng2 * 2, w0 = wg * 4;
        float acc[2][4];
        #pragma unroll
        for (int j = 0; j < 2; j++)
            #pragma unroll
            for (int l = 0; l < 4; l++) acc[j][l] = 0.f;
        #pragma unroll 4
        for (int rr = 0; rr < 64; rr++) {
            float q0 = qs[i0][rr];
            float q1 = qs[i0 + 1][rr];
            float kv[5];
            #pragma unroll
            for (int m = 0; m < 5; m++) kv[m] = ks[i0 + w0 + m][rr];
            #pragma unroll
            for (int l = 0; l < 4; l++) {
                acc[0][l] += q0 * kv[l];
                acc[1][l] += q1 * kv[l + 1];
            }
        }
        #pragma unroll
        for (int l = 0; l < 4; l++) {
            sc[i0][w0 + l]     = acc[0][l] * SCALE;
            sc[i0 + 1][w0 + l] = acc[1][l] * SCALE;
        }
    }
    if (t < 64) {
        int i = t >> 1, w = 64 + (t & 1);
        float acc = 0.f;
        if (w == 64) {
            #pragma unroll 8
            for (int rr = 0; rr < 64; rr++) acc += qs[i][rr] * ks[i + 64][rr];
        } else {
            #pragma unroll 8
            for (int rr = 0; rr < 64; rr++) acc += qs[i][rr] * k0[rr];
        }
        sc[i][w] = acc * SCALE;
    }
    __syncthreads();

    int warp = t >> 5, lane = t & 31;
    for (int i = warp; i < 32; i += 8) {
        int n = n0 + i;
        if (n >= N_) continue;
        int w0 = lane, w1 = lane + 32, w2 = (lane < 2) ? 64 + lane : -1;
        float s0 = sc[i][w0], s1 = sc[i][w1];
        float s2 = (w2 >= 0) ? sc[i][w2] : 0.f;
        bool v0 = edge_valid(n, w0);
        bool v1 = edge_valid(n, w1);
        bool v2 = (w2 >= 0) ? edge_valid(n, w2) : false;
        float mx = fmaxf(v0 ? fabsf(s0) : -1e30f,
                   fmaxf(v1 ? fabsf(s1) : -1e30f,
                         v2 ? fabsf(s2) : -1e30f));
        #pragma unroll
        for (int o = 16; o; o >>= 1) mx = fmaxf(mx, __shfl_xor_sync(0xffffffffu, mx, o));
        float e0 = v0 ? expf(fabsf(s0) - mx) : 0.f;
        float e1 = v1 ? expf(fabsf(s1) - mx) : 0.f;
        float e2 = v2 ? expf(fabsf(s2) - mx) : 0.f;
        float sum = e0 + e1 + e2;
        #pragma unroll
        for (int o = 16; o; o >>= 1) sum += __shfl_xor_sync(0xffffffffu, sum, o);
        float invs = 1.f / sum;
        float we0 = sgnf(s0) * e0 * invs;
        float we1 = sgnf(s1) * e1 * invs;
        float we2 = sgnf(s2) * e2 * invs;
        size_t o_ = (base + n) * E_;
        g_we[o_ + w0] = we0;
        g_we[o_ + w1] = we1;
        if (w2 >= 0) g_we[o_ + w2] = we2;
        float ds = we0 * st[i + w0] + we1 * st[i + w1];
        if (lane == 0) ds += we2 * st[i + 64];
        if (lane == 1) ds += we2 * st[96];
        #pragma unroll
        for (int o = 16; o; o >>= 1) ds += __shfl_xor_sync(0xffffffffu, ds, o);
        if (lane == 0) g_dstate[base + n] = ds;
    }
}

// ---------------- K4: dval propagation (R6 layout + FFMA2) ----------------
// block = 64 nodes x 64 feats, 256 threads, thread = 4 nodes x 4 feats
#define DV_NODES 64
#define DV_FEATS 64
#define DV_ROWS  128
#define DV_VSTR  68
#define DV_WSTR  76
// dyn smem: vs[128][68] | wz[64][76] | wa[64] | v0s[64]  = 54784 B
#define DV_SMEM_FLOATS (DV_ROWS*DV_VSTR + DV_NODES*DV_WSTR + DV_NODES + DV_FEATS)

__global__ __launch_bounds__(256, 4) void k_dval() {
    extern __shared__ float sm[];
    float* vs  = sm;                                 // [128][68]
    float* wz  = vs + DV_ROWS * DV_VSTR;             // [64][76], zero-padded
    float* wa  = wz + DV_NODES * DV_WSTR;            // [64]
    float* v0s = wa + DV_NODES;                      // [64]

    int b  = blockIdx.z;
    int dc = blockIdx.y * DV_FEATS;
    int n0 = blockIdx.x * DV_NODES;
    int t  = threadIdx.x;
    size_t base = (size_t)b * N_;

    for (int i = t; i < DV_ROWS * (DV_FEATS / 4); i += 256) {
        int row = i >> 4, c4 = i & 15;
        int g = min(max(n0 - WINW + row, 0), N_ - 1);
        float4 v = *(const float4*)&g_val[(base + g) * D_ + dc + c4 * 4];
        *(float4*)&vs[row * DV_VSTR + c4 * 4] = v;
    }
    for (int i = t; i < DV_NODES * DV_WSTR; i += 256) wz[i] = 0.f;
    if (t < 16) *(float4*)&v0s[t * 4] = *(const float4*)&g_val[base * D_ + dc + t * 4];
    __syncthreads();
    for (int i = t; i < DV_NODES * 65; i += 256) {
        int node = i / 65, w = i % 65;
        int g = n0 + node; if (g >= N_) g = N_ - 1;
        wz[node * DV_WSTR + w + 8] = g_we[(base + g) * E_ + w];
    }
    if (t < DV_NODES) {
        int g = n0 + t; if (g >= N_) g = N_ - 1;
        wa[t] = g_we[(base + g) * E_ + 65];
    }
    __syncthreads();

    int fg = t & 15;          // feat group -> 4 feats
    int ng = t >> 4;          // node group -> 4 nodes
    int i0 = ng * 4;
    int f0 = fg * 4;

    // packed accumulators: acc01[j] = (a[j].x, a[j].y), acc23[j] = (a[j].z, a[j].w)
    unsigned long long acc01[4], acc23[4];
    #pragma unroll
    for (int j = 0; j < 4; j++) { acc01[j] = 0ull; acc23[j] = 0ull; }

    // r = i0 + rr; weight for node (i0+j) is wz[i0+j][rr - j + 8]
    #pragma unroll 4
    for (int rr = 0; rr < 68; rr++) {
        int r = i0 + rr;
        float w0f = wz[(i0 + 0) * DV_WSTR + rr + 8];
        float w1f = wz[(i0 + 1) * DV_WSTR + rr + 7];
        float w2f = wz[(i0 + 2) * DV_WSTR + rr + 6];
        float w3f = wz[(i0 + 3) * DV_WSTR + rr + 5];
        ulonglong2 vv = *(const ulonglong2*)&vs[r * DV_VSTR + f0];
        unsigned long long wp;
        wp = pk2(w0f, w0f); fma2(acc01[0], wp, vv.x, acc01[0]); fma2(acc23[0], wp, vv.y, acc23[0]);
        wp = pk2(w1f, w1f); fma2(acc01[1], wp, vv.x, acc01[1]); fma2(acc23[1], wp, vv.y, acc23[1]);
        wp = pk2(w2f, w2f); fma2(acc01[2], wp, vv.x, acc01[2]); fma2(acc23[2], wp, vv.y, acc23[2]);
        wp = pk2(w3f, w3f); fma2(acc01[3], wp, vv.x, acc01[3]); fma2(acc23[3], wp, vv.y, acc23[3]);
    }
    // unpack + anchor edge + store
    float4 va = *(const float4*)&v0s[f0];
    #pragma unroll
    for (int j = 0; j < 4; j++) {
        float4 a;
        upk2(a.x, a.y, acc01[j]);
        upk2(a.z, a.w, acc23[j]);
        float wtj = wa[i0 + j];
        a.x += wtj * va.x; a.y += wtj * va.y;
        a.z += wtj * va.z; a.w += wtj * va.w;
        int n = n0 + i0 + j;
        if (n < N_) {
            *(float4*)&g_dval[(base + n) * D_ + dc + f0] = a;
        }
    }
}

// ---------------- K5: residual + LayerNorm + state update ----------------
__global__ void k_ln(const float* __restrict__ lng, const float* __restrict__ lnb,
                     int layer, float* __restrict__ out) {
    __shared__ float sh[8];
    int bn = blockIdx.x;
    int t  = threadIdx.x;
    float* vrow = g_val  + (size_t)bn * D_;
    float* drow = g_dval + (size_t)bn * D_;
    const float* g  = lng + (size_t)layer * D_;
    const float* bt = lnb + (size_t)layer * D_;
    float x0 = vrow[t]       + drow[t];
    float x1 = vrow[t + 256] + drow[t + 256];
    float m  = blkSum256(x0 + x1, sh) * (1.f / D_);
    float d0 = x0 - m, d1 = x1 - m;
    float var = blkSum256(d0 * d0 + d1 * d1, sh) * (1.f / D_);
    float inv = rsqrtf(var + 1e-5f);
    float y0 = d0 * inv * g[t]       + bt[t];
    float y1 = d1 * inv * g[t + 256] + bt[t + 256];
    float* vdst = out ? (out + M_ + (size_t)bn * D_) : vrow;
    vdst[t]       = y0;
    vdst[t + 256] = y1;
    if (t == 0) {
        float s = g_state[bn] + g_dstate[bn];
        if (out) out[bn] = s;
        else     g_state[bn] = s;
    }
}

// ---------------- host ----------------
extern "C" void kernel_launch(void* const* d_in, const int* in_sizes, int n_in,
                              void* d_out, int out_size) {
    const int*   ids  = (const int*)  d_in[0];
    const float* emb  = (const float*)d_in[1];
    const float* pos  = (const float*)d_in[2];
    const float* aval = (const float*)d_in[3];
    const float* ast  = (const float*)d_in[4];
    const float* ing  = (const float*)d_in[5];
    const float* inb  = (const float*)d_in[6];
    const float* spw  = (const float*)d_in[7];
    const float* spb  = (const float*)d_in[8];
    const float* wq   = (const float*)d_in[9];
    const float* wk   = (const float*)d_in[10];
    const float* lng  = (const float*)d_in[11];
    const float* lnb  = (const float*)d_in[12];
    float* out = (float*)d_out;

    const int dv_smem = DV_SMEM_FLOATS * 4;
    cudaFuncSetAttribute(k_dval, cudaFuncAttributeMaxDynamicSharedMemorySize, dv_smem);

    k_embed<<<M_, 256>>>(ids, emb, pos, aval, ast, ing, inb, spw, spb);
    for (int l = 0; l < L_; l++) {
        k_proj  <<<(M_ + 31) / 32, 128>>>(wq, wk, l);
        k_scores<<<dim3(65, B_), 256>>>();
        k_dval  <<<dim3((N_ + DV_NODES - 1) / DV_NODES, D_ / DV_FEATS, B_), 256, dv_smem>>>();
        k_ln    <<<M_, 256>>>(lng, lnb, l, (l == L_ - 1) ? out : nullptr);
    }
}

// round 11
// speedup vs baseline: 1.0973x; 1.0126x over previous
#include <cuda_runtime.h>
#include <math.h>

#define B_   4
#define S_   2048
#define N_   2049
#define D_   512
#define R_   64
#define L_   2
#define WINW 32
#define E_   66      // 65 window edges + anchor
#define M_   (B_*N_)
#define SCALE 0.125f

// ---------------- scratch (no allocs allowed) ----------------
__device__ float g_val[M_*D_];
__device__ float g_dval[M_*D_];
__device__ float g_q[M_*R_];
__device__ float g_k[M_*R_];
__device__ float g_we[M_*E_];
__device__ float g_state[M_];
__device__ float g_dstate[M_];

// ---------------- packed f32x2 helpers (Blackwell FFMA2) ----------------
__device__ __forceinline__ unsigned long long pk2(float x, float y) {
    unsigned long long r;
    asm("mov.b64 %0, {%1, %2};" : "=l"(r) : "f"(x), "f"(y));
    return r;
}
__device__ __forceinline__ void fma2(unsigned long long& d, unsigned long long a,
                                     unsigned long long b, unsigned long long c) {
    asm("fma.rn.f32x2 %0, %1, %2, %3;" : "=l"(d) : "l"(a), "l"(b), "l"(c));
}
__device__ __forceinline__ void upk2(float& x, float& y, unsigned long long v) {
    asm("mov.b64 {%0, %1}, %2;" : "=f"(x), "=f"(y) : "l"(v));
}

// ---------------- block reduction (256 threads) ----------------
__device__ __forceinline__ float blkSum256(float v, float* sh) {
    int lane = threadIdx.x & 31, w = threadIdx.x >> 5;
    #pragma unroll
    for (int o = 16; o; o >>= 1) v += __shfl_xor_sync(0xffffffffu, v, o);
    if (lane == 0) sh[w] = v;
    __syncthreads();
    if (w == 0) {
        float x = (lane < 8) ? sh[lane] : 0.f;
        #pragma unroll
        for (int o = 4; o; o >>= 1) x += __shfl_xor_sync(0xffffffffu, x, o);
        if (lane == 0) sh[0] = x;
    }
    __syncthreads();
    float r = sh[0];
    __syncthreads();
    return r;
}

// ---------------- K1: embedding + input LN + state proj ----------------
__global__ void k_embed(const int* __restrict__ ids, const float* __restrict__ emb,
                        const float* __restrict__ pos, const float* __restrict__ aval,
                        const float* __restrict__ ast,
                        const float* __restrict__ ing, const float* __restrict__ inb,
                        const float* __restrict__ spw, const float* __restrict__ spb) {
    __shared__ float sh[8];
    int bn = blockIdx.x;
    int b = bn / N_, n = bn % N_;
    float* vrow = g_val + (size_t)bn * D_;
    int t = threadIdx.x;
    if (n == 0) {
        vrow[t]       = aval[t];
        vrow[t + 256] = aval[t + 256];
        if (t == 0) g_state[bn] = ast[0];
        return;
    }
    int id = ids[b * S_ + (n - 1)];
    float x0 = emb[(size_t)id * D_ + t]       + pos[(size_t)(n - 1) * D_ + t];
    float x1 = emb[(size_t)id * D_ + t + 256] + pos[(size_t)(n - 1) * D_ + t + 256];
    float m  = blkSum256(x0 + x1, sh) * (1.f / D_);
    float d0 = x0 - m, d1 = x1 - m;
    float var = blkSum256(d0 * d0 + d1 * d1, sh) * (1.f / D_);
    float inv = rsqrtf(var + 1e-5f);
    float y0 = d0 * inv * ing[t]       + inb[t];
    float y1 = d1 * inv * ing[t + 256] + inb[t + 256];
    vrow[t] = y0; vrow[t + 256] = y1;
    float dp = blkSum256(y0 * spw[t] + y1 * spw[t + 256], sh);
    if (t == 0) g_state[bn] = dp + spb[0];
}

// ---------------- K2: q/k projection  [M,512] @ [512,128], FFMA2 ----------------
__global__ __launch_bounds__(128) void k_proj(const float* __restrict__ wq,
                                              const float* __restrict__ wk, int layer) {
    __shared__ float As[32][36];    // [row][kk]
    __shared__ float Bs[32][132];   // [kk][col] cols 0..63=q, 64..127=k
    int m0 = blockIdx.x * 32;
    const float* wqL = wq + (size_t)layer * D_ * R_;
    const float* wkL = wk + (size_t)layer * D_ * R_;
    int t  = threadIdx.x;
    int cg = t & 15;
    int rg = t >> 4;
    unsigned long long q01[4], q23[4], k01[4], k23[4];
    #pragma unroll
    for (int i = 0; i < 4; i++) { q01[i] = 0ull; q23[i] = 0ull; k01[i] = 0ull; k23[i] = 0ull; }

    for (int kc = 0; kc < D_; kc += 32) {
        #pragma unroll
        for (int i = t; i < 32 * 8; i += 128) {
            int row = i >> 3, kq = (i & 7) * 4;
            int gr = m0 + row; if (gr >= M_) gr = M_ - 1;
            float4 v = *(const float4*)&g_val[(size_t)gr * D_ + kc + kq];
            *(float4*)&As[row][kq] = v;
        }
        #pragma unroll
        for (int i = t; i < 32 * 32; i += 128) {
            int kk = i >> 5, c4 = (i & 31) * 4;
            float4 v;
            if (c4 < 64) v = *(const float4*)&wqL[(size_t)(kc + kk) * R_ + c4];
            else         v = *(const float4*)&wkL[(size_t)(kc + kk) * R_ + (c4 - 64)];
            *(float4*)&Bs[kk][c4] = v;
        }
        __syncthreads();
        #pragma unroll 8
        for (int kk = 0; kk < 32; kk++) {
            unsigned long long ap[4];
            #pragma unroll
            for (int i = 0; i < 4; i++) {
                float av = As[rg * 4 + i][kk];
                ap[i] = pk2(av, av);
            }
            ulonglong2 bq = *(const ulonglong2*)&Bs[kk][cg * 4];
            ulonglong2 bk = *(const ulonglong2*)&Bs[kk][64 + cg * 4];
            #pragma unroll
            for (int i = 0; i < 4; i++) {
                fma2(q01[i], ap[i], bq.x, q01[i]);
                fma2(q23[i], ap[i], bq.y, q23[i]);
                fma2(k01[i], ap[i], bk.x, k01[i]);
                fma2(k23[i], ap[i], bk.y, k23[i]);
            }
        }
        __syncthreads();
    }
    #pragma unroll
    for (int i = 0; i < 4; i++) {
        int gr = m0 + rg * 4 + i;
        if (gr >= M_) continue;
        float4 oq, ok;
        upk2(oq.x, oq.y, q01[i]); upk2(oq.z, oq.w, q23[i]);
        upk2(ok.x, ok.y, k01[i]); upk2(ok.z, ok.w, k23[i]);
        *(float4*)&g_q[(size_t)gr * R_ + cg * 4] = oq;
        *(float4*)&g_k[(size_t)gr * R_ + cg * 4] = ok;
    }
}

// ---------------- K3: scores + signed-abs softmax + dstate ----------------
__device__ __forceinline__ bool edge_valid(int n, int w) {
    if (w < 65) { int p = n + w - WINW; return (p >= 0) && (p < N_); }
    return n > WINW;
}
__device__ __forceinline__ float sgnf(float s) {
    return (s > 0.f) ? 1.f : ((s < 0.f) ? -1.f : 0.f);
}

#define KS_STR 65
__global__ void k_scores() {
    __shared__ float ks[96][KS_STR];
    __shared__ float qs[32][KS_STR];
    __shared__ float k0[64];
    __shared__ float st[97];
    __shared__ float sc[32][68];
    int b  = blockIdx.y;
    int n0 = blockIdx.x * 32;
    int t  = threadIdx.x;
    size_t base = (size_t)b * N_;

    for (int i = t; i < 96 * 64; i += 256) {
        int r = i >> 6, rr = i & 63;
        int g = n0 - WINW + r; g = min(max(g, 0), N_ - 1);
        ks[r][rr] = g_k[(base + g) * R_ + rr];
    }
    for (int i = t; i < 32 * 64; i += 256) {
        int r = i >> 6, rr = i & 63;
        int g = n0 + r; if (g >= N_) g = N_ - 1;
        qs[r][rr] = g_q[(base + g) * R_ + rr];
    }
    if (t < 64) k0[t] = g_k[base * R_ + t];
    if (t < 96) { int g = min(max(n0 - WINW + t, 0), N_ - 1); st[t] = g_state[base + g]; }
    if (t == 96) st[96] = g_state[base];
    __syncthreads();

    {
        int ng2 = t >> 4;
        int wg  = t & 15;
        int i0 = ng2 * 2, w0 = wg * 4;
        float acc[2][4];
        #pragma unroll
        for (int j = 0; j < 2; j++)
            #pragma unroll
            for (int l = 0; l < 4; l++) acc[j][l] = 0.f;
        #pragma unroll 4
        for (int rr = 0; rr < 64; rr++) {
            float q0 = qs[i0][rr];
            float q1 = qs[i0 + 1][rr];
            float kv[5];
            #pragma unroll
            for (int m = 0; m < 5; m++) kv[m] = ks[i0 + w0 + m][rr];
            #pragma unroll
            for (int l = 0; l < 4; l++) {
                acc[0][l] += q0 * kv[l];
                acc[1][l] += q1 * kv[l + 1];
            }
        }
        #pragma unroll
        for (int l = 0; l < 4; l++) {
            sc[i0][w0 + l]     = acc[0][l] * SCALE;
            sc[i0 + 1][w0 + l] = acc[1][l] * SCALE;
        }
    }
    if (t < 64) {
        int i = t >> 1, w = 64 + (t & 1);
        float acc = 0.f;
        if (w == 64) {
            #pragma unroll 8
            for (int rr = 0; rr < 64; rr++) acc += qs[i][rr] * ks[i + 64][rr];
        } else {
            #pragma unroll 8
            for (int rr = 0; rr < 64; rr++) acc += qs[i][rr] * k0[rr];
        }
        sc[i][w] = acc * SCALE;
    }
    __syncthreads();

    int warp = t >> 5, lane = t & 31;
    for (int i = warp; i < 32; i += 8) {
        int n = n0 + i;
        if (n >= N_) continue;
        int w0 = lane, w1 = lane + 32, w2 = (lane < 2) ? 64 + lane : -1;
        float s0 = sc[i][w0], s1 = sc[i][w1];
        float s2 = (w2 >= 0) ? sc[i][w2] : 0.f;
        bool v0 = edge_valid(n, w0);
        bool v1 = edge_valid(n, w1);
        bool v2 = (w2 >= 0) ? edge_valid(n, w2) : false;
        float mx = fmaxf(v0 ? fabsf(s0) : -1e30f,
                   fmaxf(v1 ? fabsf(s1) : -1e30f,
                         v2 ? fabsf(s2) : -1e30f));
        #pragma unroll
        for (int o = 16; o; o >>= 1) mx = fmaxf(mx, __shfl_xor_sync(0xffffffffu, mx, o));
        float e0 = v0 ? expf(fabsf(s0) - mx) : 0.f;
        float e1 = v1 ? expf(fabsf(s1) - mx) : 0.f;
        float e2 = v2 ? expf(fabsf(s2) - mx) : 0.f;
        float sum = e0 + e1 + e2;
        #pragma unroll
        for (int o = 16; o; o >>= 1) sum += __shfl_xor_sync(0xffffffffu, sum, o);
        float invs = 1.f / sum;
        float we0 = sgnf(s0) * e0 * invs;
        float we1 = sgnf(s1) * e1 * invs;
        float we2 = sgnf(s2) * e2 * invs;
        size_t o_ = (base + n) * E_;
        g_we[o_ + w0] = we0;
        g_we[o_ + w1] = we1;
        if (w2 >= 0) g_we[o_ + w2] = we2;
        float ds = we0 * st[i + w0] + we1 * st[i + w1];
        if (lane == 0) ds += we2 * st[i + 64];
        if (lane == 1) ds += we2 * st[96];
        #pragma unroll
        for (int o = 16; o; o >>= 1) ds += __shfl_xor_sync(0xffffffffu, ds, o);
        if (lane == 0) g_dstate[base + n] = ds;
    }
}

// ---------------- K4: dval (FFMA2 + shift-aligned vector weights + fused residual) ----------------
// block = 64 nodes x 64 feats, 256 threads, thread = 4 nodes x 4 feats
// weight storage: wz[node][w + 8 + (node&3)] so that the weight needed at row rr
// for node i0+j sits at index rr+8 for ALL j -> one LDS.128 per node per 4 rows.
// Output g_dval carries val + dval (residual folded in); k_ln reads it alone.
#define DV_NODES 64
#define DV_FEATS 64
#define DV_ROWS  128
#define DV_VSTR  68
#define DV_WSTR  76
// dyn smem: vs[128][68] | wz[64][76] | wa[64] | v0s[64]  = 54784 B
#define DV_SMEM_FLOATS (DV_ROWS*DV_VSTR + DV_NODES*DV_WSTR + DV_NODES + DV_FEATS)

__global__ __launch_bounds__(256, 4) void k_dval() {
    extern __shared__ float sm[];
    float* vs  = sm;                                 // [128][68]
    float* wz  = vs + DV_ROWS * DV_VSTR;             // [64][76], zero-padded, shift-stored
    float* wa  = wz + DV_NODES * DV_WSTR;            // [64]
    float* v0s = wa + DV_NODES;                      // [64]

    int b  = blockIdx.z;
    int dc = blockIdx.y * DV_FEATS;
    int n0 = blockIdx.x * DV_NODES;
    int t  = threadIdx.x;
    size_t base = (size_t)b * N_;

    for (int i = t; i < DV_ROWS * (DV_FEATS / 4); i += 256) {
        int row = i >> 4, c4 = i & 15;
        int g = min(max(n0 - WINW + row, 0), N_ - 1);
        float4 v = *(const float4*)&g_val[(base + g) * D_ + dc + c4 * 4];
        *(float4*)&vs[row * DV_VSTR + c4 * 4] = v;
    }
    for (int i = t; i < DV_NODES * DV_WSTR; i += 256) wz[i] = 0.f;
    if (t < 16) *(float4*)&v0s[t * 4] = *(const float4*)&g_val[base * D_ + dc + t * 4];
    __syncthreads();
    // shifted fill: wz[node][w + 8 + (node&3)] = we[node][w]
    for (int i = t; i < DV_NODES * 65; i += 256) {
        int node = i / 65, w = i % 65;
        int g = n0 + node; if (g >= N_) g = N_ - 1;
        wz[node * DV_WSTR + w + 8 + (node & 3)] = g_we[(base + g) * E_ + w];
    }
    if (t < DV_NODES) {
        int g = n0 + t; if (g >= N_) g = N_ - 1;
        wa[t] = g_we[(base + g) * E_ + 65];
    }
    __syncthreads();

    int fg = t & 15;          // feat group -> 4 feats
    int ng = t >> 4;          // node group -> 4 nodes
    int i0 = ng * 4;
    int f0 = fg * 4;

    unsigned long long acc01[4], acc23[4];
    #pragma unroll
    for (int j = 0; j < 4; j++) { acc01[j] = 0ull; acc23[j] = 0ull; }

    const float* wb0 = wz + (i0 + 0) * DV_WSTR + 8;
    const float* wb1 = wz + (i0 + 1) * DV_WSTR + 8;
    const float* wb2 = wz + (i0 + 2) * DV_WSTR + 8;
    const float* wb3 = wz + (i0 + 3) * DV_WSTR + 8;

    // 68 rows in 17 chunks of 4; weight index rr+8 identical for all 4 nodes
    #pragma unroll 2
    for (int c = 0; c < 17; c++) {
        float4 w0v = *(const float4*)(wb0 + 4 * c);
        float4 w1v = *(const float4*)(wb1 + 4 * c);
        float4 w2v = *(const float4*)(wb2 + 4 * c);
        float4 w3v = *(const float4*)(wb3 + 4 * c);
        const float* vbase = &vs[(i0 + 4 * c) * DV_VSTR + f0];
        #pragma unroll
        for (int m = 0; m < 4; m++) {
            ulonglong2 vv = *(const ulonglong2*)(vbase + m * DV_VSTR);
            float wm0 = (&w0v.x)[m], wm1 = (&w1v.x)[m];
            float wm2 = (&w2v.x)[m], wm3 = (&w3v.x)[m];
            unsigned long long wp;
            wp = pk2(wm0, wm0); fma2(acc01[0], wp, vv.x, acc01[0]); fma2(acc23[0], wp, vv.y, acc23[0]);
            wp = pk2(wm1, wm1); fma2(acc01[1], wp, vv.x, acc01[1]); fma2(acc23[1], wp, vv.y, acc23[1]);
            wp = pk2(wm2, wm2); fma2(acc01[2], wp, vv.x, acc01[2]); fma2(acc23[2], wp, vv.y, acc23[2]);
            wp = pk2(wm3, wm3); fma2(acc01[3], wp, vv.x, acc01[3]); fma2(acc23[3], wp, vv.y, acc23[3]);
        }
    }
    // unpack + anchor edge + residual (vs row i0+j+32 = this node's own val) + store
    float4 va = *(const float4*)&v0s[f0];
    #pragma unroll
    for (int j = 0; j < 4; j++) {
        float4 a;
        upk2(a.x, a.y, acc01[j]);
        upk2(a.z, a.w, acc23[j]);
        float wtj = wa[i0 + j];
        float4 rv = *(const float4*)&vs[(i0 + j + 32) * DV_VSTR + f0];
        a.x += wtj * va.x + rv.x; a.y += wtj * va.y + rv.y;
        a.z += wtj * va.z + rv.z; a.w += wtj * va.w + rv.w;
        int n = n0 + i0 + j;
        if (n < N_) {
            *(float4*)&g_dval[(base + n) * D_ + dc + f0] = a;
        }
    }
}

// ---------------- K5: LayerNorm(g_dval = val+dval) + state update ----------------
__global__ void k_ln(const float* __restrict__ lng, const float* __restrict__ lnb,
                     int layer, float* __restrict__ out) {
    __shared__ float sh[8];
    int bn = blockIdx.x;
    int t  = threadIdx.x;
    float* vrow = g_val  + (size_t)bn * D_;
    float* drow = g_dval + (size_t)bn * D_;
    const float* g  = lng + (size_t)layer * D_;
    const float* bt = lnb + (size_t)layer * D_;
    float x0 = drow[t];          // residual already folded in by k_dval
    float x1 = drow[t + 256];
    float m  = blkSum256(x0 + x1, sh) * (1.f / D_);
    float d0 = x0 - m, d1 = x1 - m;
    float var = blkSum256(d0 * d0 + d1 * d1, sh) * (1.f / D_);
    float inv = rsqrtf(var + 1e-5f);
    float y0 = d0 * inv * g[t]       + bt[t];
    float y1 = d1 * inv * g[t + 256] + bt[t + 256];
    float* vdst = out ? (out + M_ + (size_t)bn * D_) : vrow;
    vdst[t]       = y0;
    vdst[t + 256] = y1;
    if (t == 0) {
        float s = g_state[bn] + g_dstate[bn];
        if (out) out[bn] = s;
        else     g_state[bn] = s;
    }
}

// ---------------- host ----------------
extern "C" void kernel_launch(void* const* d_in, const int* in_sizes, int n_in,
                              void* d_out, int out_size) {
    const int*   ids  = (const int*)  d_in[0];
    const float* emb  = (const float*)d_in[1];
    const float* pos  = (const float*)d_in[2];
    const float* aval = (const float*)d_in[3];
    const float* ast  = (const float*)d_in[4];
    const float* ing  = (const float*)d_in[5];
    const float* inb  = (const float*)d_in[6];
    const float* spw  = (const float*)d_in[7];
    const float* spb  = (const float*)d_in[8];
    const float* wq   = (const float*)d_in[9];
    const float* wk   = (const float*)d_in[10];
    const float* lng  = (const float*)d_in[11];
    const float* lnb  = (const float*)d_in[12];
    float* out = (float*)d_out;

    const int dv_smem = DV_SMEM_FLOATS * 4;
    cudaFuncSetAttribute(k_dval, cudaFuncAttributeMaxDynamicSharedMemorySize, dv_smem);

    k_embed<<<M_, 256>>>(ids, emb, pos, aval, ast, ing, inb, spw, spb);
    for (int l = 0; l < L_; l++) {
        k_proj  <<<(M_ + 31) / 32, 128>>>(wq, wk, l);
        k_scores<<<dim3(65, B_), 256>>>();
        k_dval  <<<dim3((N_ + DV_NODES - 1) / DV_NODES, D_ / DV_FEATS, B_), 256, dv_smem>>>();
        k_ln    <<<M_, 256>>>(lng, lnb, l, (l == L_ - 1) ? out : nullptr);
    }
}